// round 14
// baseline (speedup 1.0000x reference)
#include <cuda_runtime.h>
#include <cuda_fp16.h>
#include <cstdint>

// ---------------------------------------------------------------------------
// y = sum_b ((x*v2_b) @ sign(V_b)^T * (v1_b*u2_b)) @ sign(U_b)^T * u1_b + bias
// Binary +-1 weights -> exact 2:4 sparsity (pair transform), mma.sp
// ::ordered_metadata.m16n8k32. Measured invariant: mma.sp acceptance ~22.8
// cyc/instr/SMSP (warp-count/reg/smem independent) -> GEMMs at floor.
// R13: R11 record GEMM config verbatim; prep gets streaming cache hints
// (.cs) + 2x ILP in prep_x to squeeze the last DRAM efficiency.
// ---------------------------------------------------------------------------

#define WTILE 128   // weight rows per CTA
#define XT 128      // batch cols per CTA
#define STG 3
#define AROWB 80    // compressed A row: 32 halfs (64B) padded to 80
#define BROWB 144   // B row: 64 halfs (128B) padded to 144
#define SPA (WTILE*AROWB)         // 10240
#define SPB (XT*BROWB)            // 18432
#define SPM 1024                  // meta per stage
#define STGB (SPA+SPB+SPM)        // 29696
#define SMEMB (STG*STGB)          // 89088

__device__ __align__(16) __half   g_xp[2ull*8192*4096];   // x' pairs per branch
__device__ __align__(16) __half   g_cv[2ull*1024*2048];   // compressed sgn(V)
__device__ __align__(16) __half   g_cu[4096ull*1024];     // compressed sgn(U)*u1 (concat)
__device__ __align__(16) __half   g_hp[8192ull*2048];     // H' pairs
__device__ __align__(16) uint32_t g_mv[2ull*64*128*16];   // metadata V (both branches)
__device__ __align__(16) uint32_t g_mu[256ull*64*16];     // metadata Ucat
__device__ float g_s1[2048];

__device__ __forceinline__ uint32_t smem_u32(const void* p){
  uint32_t a;
  asm("{ .reg .u64 t; cvta.to.shared.u64 t, %1; cvt.u32.u64 %0, t; }" : "=r"(a) : "l"(p));
  return a;
}
__device__ __forceinline__ void cp16(uint32_t dst, const void* src){
  asm volatile("cp.async.cg.shared.global [%0], [%1], 16;" :: "r"(dst), "l"(src));
}
__device__ __forceinline__ void cp8(uint32_t dst, const void* src){
  asm volatile("cp.async.ca.shared.global [%0], [%1], 8;" :: "r"(dst), "l"(src));
}
__device__ __forceinline__ void ldsm4(uint32_t& r0, uint32_t& r1, uint32_t& r2,
                                      uint32_t& r3, uint32_t addr){
  asm volatile("ldmatrix.sync.aligned.m8n8.x4.shared.b16 {%0,%1,%2,%3}, [%4];"
    : "=r"(r0), "=r"(r1), "=r"(r2), "=r"(r3) : "r"(addr));
}
__device__ __forceinline__ void mma_sp(float* d, const uint32_t* a,
                                       const uint32_t* b, uint32_t e){
  asm volatile("mma.sp::ordered_metadata.sync.aligned.m16n8k32.row.col.f32.f16.f16.f32 "
    "{%0,%1,%2,%3}, {%4,%5,%6,%7}, {%8,%9,%10,%11}, {%0,%1,%2,%3}, %12, 0x0;"
    : "+f"(d[0]), "+f"(d[1]), "+f"(d[2]), "+f"(d[3])
    : "r"(a[0]), "r"(a[1]), "r"(a[2]), "r"(a[3]),
      "r"(b[0]), "r"(b[1]), "r"(b[2]), "r"(b[3]), "r"(e));
}
__device__ __forceinline__ float sg(float v){ return v > 0.f ? 1.f : (v < 0.f ? -1.f : 0.f); }

__device__ __forceinline__ float4 ldcs4(const float4* p){
  float4 v;
  asm volatile("ld.global.nc.cs.v4.f32 {%0,%1,%2,%3}, [%4];"
    : "=f"(v.x), "=f"(v.y), "=f"(v.z), "=f"(v.w) : "l"(p));
  return v;
}
__device__ __forceinline__ void stcs2(uint2* p, uint2 v){
  asm volatile("st.global.cs.v2.u32 [%0], {%1,%2};" :: "l"(p), "r"(v.x), "r"(v.y));
}

// ------------------------------ prep: xp ------------------------------------
// x' pairs, float4 granularity, 2x ILP, streaming cache hints (x and xp are
// not re-read before eviction; keep v2 vectors cached).
__global__ void __launch_bounds__(256, 8)
prep_x_k(const float4* __restrict__ xv4, const float4* __restrict__ a4,
         const float4* __restrict__ b4){
  uint2* oA = reinterpret_cast<uint2*>(g_xp);
  uint2* oB = reinterpret_cast<uint2*>(g_xp + 8192ull*4096);
  const size_t n = 8192ull*1024;
  const size_t stride = 4096ull*256;
  size_t i0 = (size_t)blockIdx.x*256 + threadIdx.x;
  for (size_t i = i0; i < n; i += 2*stride){
    size_t j = i + stride;
    float4 xv0 = ldcs4(xv4 + i);
    float4 xv1 = (j < n) ? ldcs4(xv4 + j) : make_float4(0.f,0.f,0.f,0.f);
    {
      int t = (int)(i & 1023);
      float4 a = a4[t], b = b4[t];
      float s0 = xv0.x*a.x, s1 = xv0.y*a.y, s2 = xv0.z*a.z, s3 = xv0.w*a.w;
      __half2 h0 = __floats2half2_rn(s0 + s1, s0 - s1);
      __half2 h1 = __floats2half2_rn(s2 + s3, s2 - s3);
      uint2 oa; oa.x = *reinterpret_cast<uint32_t*>(&h0);
      oa.y = *reinterpret_cast<uint32_t*>(&h1);
      stcs2(oA + i, oa);
      float r0 = xv0.x*b.x, r1 = xv0.y*b.y, r2 = xv0.z*b.z, r3 = xv0.w*b.w;
      h0 = __floats2half2_rn(r0 + r1, r0 - r1);
      h1 = __floats2half2_rn(r2 + r3, r2 - r3);
      uint2 ob; ob.x = *reinterpret_cast<uint32_t*>(&h0);
      ob.y = *reinterpret_cast<uint32_t*>(&h1);
      stcs2(oB + i, ob);
    }
    if (j < n){
      int t = (int)(j & 1023);
      float4 a = a4[t], b = b4[t];
      float s0 = xv1.x*a.x, s1 = xv1.y*a.y, s2 = xv1.z*a.z, s3 = xv1.w*a.w;
      __half2 h0 = __floats2half2_rn(s0 + s1, s0 - s1);
      __half2 h1 = __floats2half2_rn(s2 + s3, s2 - s3);
      uint2 oa; oa.x = *reinterpret_cast<uint32_t*>(&h0);
      oa.y = *reinterpret_cast<uint32_t*>(&h1);
      stcs2(oA + j, oa);
      float r0 = xv1.x*b.x, r1 = xv1.y*b.y, r2 = xv1.z*b.z, r3 = xv1.w*b.w;
      h0 = __floats2half2_rn(r0 + r1, r0 - r1);
      h1 = __floats2half2_rn(r2 + r3, r2 - r3);
      uint2 ob; ob.x = *reinterpret_cast<uint32_t*>(&h0);
      ob.y = *reinterpret_cast<uint32_t*>(&h1);
      stcs2(oB + j, ob);
    }
  }
}

// ---------------------------- prep: weights ---------------------------------
// sections by blockIdx.x:
//   [0,512)    cv+mv : compressed sgn(V/V_R) AND metadata from one V read
//   [512,1024) cu+mu : compressed sgn(Ucat)*u1 AND metadata from one U read
//   [1024]     s1    : v1*u2 concat
__global__ void prep_w_k(const float* __restrict__ V,  const float* __restrict__ U,
                         const float* __restrict__ v1, const float* __restrict__ u2,
                         const float* __restrict__ u1,
                         const float* __restrict__ VR, const float* __restrict__ UR,
                         const float* __restrict__ v1R, const float* __restrict__ u2R,
                         const float* __restrict__ u1R){
  const int bid = blockIdx.x, tid = threadIdx.x;
  if (bid < 512){
    const size_t half = 64ull*128*16;   // words per branch
    for (size_t i = (size_t)bid*256 + tid; i < 2*half; i += 512ull*256){
      int br = i >= half;
      size_t idx = br ? i - half : i;
      const float* W = br ? VR : V;
      int w = (int)(idx & 15), q = w >> 1, s = w & 1;
      size_t cw = idx >> 4;
      int c = (int)(cw & 127);
      int b = (int)(cw >> 7);
      int r0 = b*16 + q;
      int kb = c*32 + s*16;
      const float* p0 = W + (size_t)r0*4096 + kb;
      const float* p1 = p0 + (size_t)8*4096;
      uint32_t lo = 0, hi = 0;
      uint4 cv0, cv1;
      uint32_t* c0 = reinterpret_cast<uint32_t*>(&cv0);
      uint32_t* c1 = reinterpret_cast<uint32_t*>(&cv1);
      #pragma unroll
      for (int g = 0; g < 4; g++){
        float4 a = ldcs4((const float4*)(p0 + g*4));
        float4 bb = ldcs4((const float4*)(p1 + g*4));
        lo |= ((((a.x < 0.f) == (a.y < 0.f)) ? 0u : 1u)
             | ((((a.z < 0.f) == (a.w < 0.f)) ? 2u : 3u) << 2)) << (4*g);
        hi |= ((((bb.x < 0.f) == (bb.y < 0.f)) ? 0u : 1u)
             | ((((bb.z < 0.f) == (bb.w < 0.f)) ? 2u : 3u) << 2)) << (4*g);
        __half2 ha = __floats2half2_rn(sg(a.x), sg(a.z));
        __half2 hb = __floats2half2_rn(sg(bb.x), sg(bb.z));
        c0[g] = *reinterpret_cast<uint32_t*>(&ha);
        c1[g] = *reinterpret_cast<uint32_t*>(&hb);
      }
      g_mv[(br ? half : 0) + idx] = lo | (hi << 16);
      size_t cvbase = (size_t)br*1024*2048;
      int t0 = c*16 + s*8;
      *reinterpret_cast<uint4*>(g_cv + cvbase + (size_t)r0*2048 + t0)     = cv0;
      *reinterpret_cast<uint4*>(g_cv + cvbase + (size_t)(r0+8)*2048 + t0) = cv1;
    }
  } else if (bid < 1024){
    const size_t n = 256ull*64*16;
    for (size_t idx = (size_t)(bid-512)*256 + tid; idx < n; idx += 512ull*256){
      int w = (int)(idx & 15), q = w >> 1, s = w & 1;
      size_t cw = idx >> 4;
      int c = (int)(cw & 63);
      int b = (int)(cw >> 6);
      int r0 = b*16 + q;
      int kb = c*32 + s*16;
      const float* W   = (kb < 1024) ? U  : UR;
      const float* u1v = (kb < 1024) ? u1 : u1R;
      int coff = (kb < 1024) ? kb : kb - 1024;
      const float* p0 = W + (size_t)r0*1024 + coff;
      const float* p1 = p0 + (size_t)8*1024;
      float sc0 = u1v[r0], sc1 = u1v[r0+8];
      uint32_t lo = 0, hi = 0;
      uint4 cv0, cv1;
      uint32_t* c0 = reinterpret_cast<uint32_t*>(&cv0);
      uint32_t* c1 = reinterpret_cast<uint32_t*>(&cv1);
      #pragma unroll
      for (int g = 0; g < 4; g++){
        float4 a = ldcs4((const float4*)(p0 + g*4));
        float4 bb = ldcs4((const float4*)(p1 + g*4));
        lo |= ((((a.x < 0.f) == (a.y < 0.f)) ? 0u : 1u)
             | ((((a.z < 0.f) == (a.w < 0.f)) ? 2u : 3u) << 2)) << (4*g);
        hi |= ((((bb.x < 0.f) == (bb.y < 0.f)) ? 0u : 1u)
             | ((((bb.z < 0.f) == (bb.w < 0.f)) ? 2u : 3u) << 2)) << (4*g);
        __half2 ha = __floats2half2_rn(sg(a.x)*sc0, sg(a.z)*sc0);
        __half2 hb = __floats2half2_rn(sg(bb.x)*sc1, sg(bb.z)*sc1);
        c0[g] = *reinterpret_cast<uint32_t*>(&ha);
        c1[g] = *reinterpret_cast<uint32_t*>(&hb);
      }
      g_mu[idx] = lo | (hi << 16);
      int t0 = c*16 + s*8;
      *reinterpret_cast<uint4*>(g_cu + (size_t)r0*1024 + t0)     = cv0;
      *reinterpret_cast<uint4*>(g_cu + (size_t)(r0+8)*1024 + t0) = cv1;
    }
  } else {
    for (int j = tid; j < 1024; j += 256){
      g_s1[j] = v1[j]*u2[j];
      g_s1[1024+j] = v1R[j]*u2R[j];
    }
  }
}

// --------------------------- sparse GEMM kernel -----------------------------
// R11 record shape, verbatim. D[w, b] = Wsp[w, Klog] (2:4) @ X'[b, Klog]^T.
// Weight-major in regs; smem transpose epilogue.
// MODE 0: H' = pairTransform(D * s1) fp16.  MODE 1: out[b][w] = D + bias[w].
template<int MODE>
__global__ void __launch_bounds__(128, 2)
spgemm_k(const __half* __restrict__ Ac, const uint32_t* __restrict__ Mt,
         const __half* __restrict__ Bx, int Klog,
         size_t strideAc, size_t strideMt, size_t strideBx,
         const float* __restrict__ aux, __half* __restrict__ outH,
         float* __restrict__ outF)
{
  extern __shared__ char smem[];
  const uint32_t sb = smem_u32(smem);
  const int tid = threadIdx.x, wid = tid >> 5, lane = tid & 31;
  const int wt = blockIdx.x, bt = blockIdx.y, bz = blockIdx.z;
  const int ww = wid >> 1, wb = wid & 1;   // weights ww*64.., batch wb*64..

  const int Kc = Klog >> 1;
  const int chunks = Klog >> 5;
  const __half* Acb = Ac + strideAc*bz + (size_t)wt*WTILE*Kc;
  const uint32_t* Mtb = Mt + strideMt*bz + (size_t)(wt*8)*chunks*16;
  const __half* Bxb = Bx + strideBx*bz + (size_t)bt*XT*Klog;
  const int KS = Klog / 64;

  #define LOAD_STAGE(buf, ks_) do {                                           \
    uint32_t st_ = sb + (buf)*STGB;                                           \
    uint32_t as_ = st_, bs_ = st_ + SPA, ms_ = st_ + SPA + SPB;               \
    _Pragma("unroll")                                                         \
    for (int i_ = 0; i_ < 4; i_++){                                           \
      int idx_ = tid + i_*128, r_ = idx_ >> 2, c_ = idx_ & 3;                 \
      cp16(as_ + r_*AROWB + c_*16, Acb + (size_t)r_*Kc + (ks_)*32 + c_*8);    \
    }                                                                         \
    _Pragma("unroll")                                                         \
    for (int i_ = 0; i_ < 8; i_++){                                           \
      int idx_ = tid + i_*128, r_ = idx_ >> 3, c_ = idx_ & 7;                 \
      cp16(bs_ + r_*BROWB + c_*16, Bxb + (size_t)r_*Klog + (ks_)*64 + c_*8);  \
    }                                                                         \
    { int f_ = tid*2, b_ = f_ >> 5, rem_ = f_ & 31;                           \
      int h_ = rem_ >> 4, w_ = rem_ & 15;                                     \
      cp8(ms_ + b_*128 + h_*64 + w_*4,                                        \
          Mtb + ((size_t)b_*chunks + 2*(ks_) + h_)*16 + w_); }                \
    asm volatile("cp.async.commit_group;" ::: "memory");                      \
  } while(0)

  LOAD_STAGE(0, 0);
  LOAD_STAGE(1, 1);

  float acc[4][8][4];
  #pragma unroll
  for (int i = 0; i < 4; i++)
    #pragma unroll
    for (int j = 0; j < 8; j++)
      #pragma unroll
      for (int k = 0; k < 4; k++) acc[i][j][k] = 0.f;

  const int l15 = lane & 15, l16 = lane >> 4;
  const uint32_t eOff = ((((lane >> 2) << 1) | (lane & 1)) << 2);
  int stage = 0;

  for (int ks = 0; ks < KS; ks++){
    asm volatile("cp.async.wait_group %0;" :: "n"(STG-2) : "memory");
    __syncthreads();
    if (ks + STG - 1 < KS){
      int nb = stage + (STG - 1); if (nb >= STG) nb -= STG;
      LOAD_STAGE(nb, ks + STG - 1);
    } else {
      asm volatile("cp.async.commit_group;" ::: "memory");
    }

    const uint32_t st = sb + stage*STGB;
    const uint32_t as = st, bs2 = st + SPA, ms = st + SPA + SPB;

    #pragma unroll
    for (int h = 0; h < 2; h++){
      uint32_t af[4][4], ev[4], bf[8][4];
      #pragma unroll
      for (int i = 0; i < 4; i++){
        ldsm4(af[i][0], af[i][1], af[i][2], af[i][3],
              as + (uint32_t)((ww*64 + i*16 + l15)*AROWB) + l16*16 + h*32);
        asm volatile("ld.shared.b32 %0, [%1];" : "=r"(ev[i])
          : "r"(ms + (uint32_t)((ww*4 + i)*128 + h*64) + eOff));
      }
      #pragma unroll
      for (int j = 0; j < 4; j++){
        #pragma unroll
        for (int kh = 0; kh < 2; kh++){
          uint32_t t0, t1, t2, t3;
          ldsm4(t0, t1, t2, t3,
                bs2 + (uint32_t)((wb*64 + j*16 + l15)*BROWB) + l16*16 + h*64 + kh*32);
          bf[j*2+0][kh*2+0] = t0; bf[j*2+0][kh*2+1] = t2;
          bf[j*2+1][kh*2+0] = t1; bf[j*2+1][kh*2+1] = t3;
        }
      }
      #pragma unroll
      for (int i = 0; i < 4; i++)
        #pragma unroll
        for (int j = 0; j < 8; j++)
          mma_sp(acc[i][j], af[i], bf[j], ev[i]);
    }
    if (++stage == STG) stage = 0;
  }

  asm volatile("cp.async.wait_group 0;" ::: "memory");
  __syncthreads();

  // ----------------------------- epilogue -----------------------------------
  const int qr = lane >> 2;
  const int qc = (lane & 3) * 2;

  if (MODE == 0){
    const uint32_t epi = sb + wid*8448;     // 64 x (66 halfs)
    const int jgBase = bz*1024 + wt*128 + ww*64;
    #pragma unroll
    for (int mf = 0; mf < 4; mf++){
      float sA = aux[jgBase + mf*16 + qr];
      float sB = aux[jgBase + mf*16 + qr + 8];
      #pragma unroll
      for (int nf = 0; nf < 8; nf++){
        float v0 = acc[mf][nf][0]*sA, v1 = acc[mf][nf][1]*sA;
        float v2 = acc[mf][nf][2]*sB, v3 = acc[mf][nf][3]*sB;
        float p0 = __shfl_xor_sync(0xffffffffu, v0, 4);
        float p1 = __shfl_xor_sync(0xffffffffu, v1, 4);
        float p2 = __shfl_xor_sync(0xffffffffu, v2, 4);
        float p3 = __shfl_xor_sync(0xffffffffu, v3, 4);
        bool even = (qr & 1) == 0;
        float r0 = even ? v0 + p0 : p0 - v0;
        float r1 = even ? v1 + p1 : p1 - v1;
        float r2 = even ? v2 + p2 : p2 - v2;
        float r3 = even ? v3 + p3 : p3 - v3;
        int bc = nf*8 + qc, jl = mf*16 + qr;
        uint32_t a0 = epi + (uint32_t)(bc*132 + jl*2);
        uint32_t a1 = epi + (uint32_t)((bc+1)*132 + jl*2);
        __half h0 = __float2half_rn(r0), h1 = __float2half_rn(r1);
        __half h2 = __float2half_rn(r2), h3 = __float2half_rn(r3);
        asm volatile("st.shared.b16 [%0], %1;" :: "r"(a0),      "h"(*(uint16_t*)&h0));
        asm volatile("st.shared.b16 [%0], %1;" :: "r"(a1),      "h"(*(uint16_t*)&h1));
        asm volatile("st.shared.b16 [%0], %1;" :: "r"(a0 + 16), "h"(*(uint16_t*)&h2));
        asm volatile("st.shared.b16 [%0], %1;" :: "r"(a1 + 16), "h"(*(uint16_t*)&h3));
      }
    }
    __syncwarp();
    const int colg = bz*1024 + wt*128 + ww*64 + lane*2;
    #pragma unroll 4
    for (int rb = 0; rb < 64; rb++){
      uint32_t v;
      asm volatile("ld.shared.b32 %0, [%1];" : "=r"(v) : "r"(epi + (uint32_t)(rb*132 + lane*4)));
      *reinterpret_cast<uint32_t*>(outH + (size_t)(bt*128 + wb*64 + rb)*2048 + colg) = v;
    }
  } else {
    const uint32_t epi = sb + wid*16896;    // 64 x (66 floats)
    #pragma unroll
    for (int mf = 0; mf < 4; mf++){
      #pragma unroll
      for (int nf = 0; nf < 8; nf++){
        int bc = nf*8 + qc, jl = mf*16 + qr;
        uint32_t a0 = epi + (uint32_t)(bc*264 + jl*4);
        uint32_t a1 = epi + (uint32_t)((bc+1)*264 + jl*4);
        asm volatile("st.shared.f32 [%0], %1;" :: "r"(a0),      "f"(acc[mf][nf][0]));
        asm volatile("st.shared.f32 [%0], %1;" :: "r"(a1),      "f"(acc[mf][nf][1]));
        asm volatile("st.shared.f32 [%0], %1;" :: "r"(a0 + 32), "f"(acc[mf][nf][2]));
        asm volatile("st.shared.f32 [%0], %1;" :: "r"(a1 + 32), "f"(acc[mf][nf][3]));
      }
    }
    __syncwarp();
    const int c0 = wt*128 + ww*64 + lane*2;
    float2 bb = *reinterpret_cast<const float2*>(aux + c0);
    #pragma unroll 4
    for (int rb = 0; rb < 64; rb++){
      float2 v;
      asm volatile("ld.shared.v2.f32 {%0,%1}, [%2];" : "=f"(v.x), "=f"(v.y)
        : "r"(epi + (uint32_t)(rb*264 + lane*8)));
      v.x += bb.x; v.y += bb.y;
      *reinterpret_cast<float2*>(outF + (size_t)(bt*128 + wb*64 + rb)*4096 + c0) = v;
    }
  }
  #undef LOAD_STAGE
}

// ----------------------------- launch ---------------------------------------
extern "C" void kernel_launch(void* const* d_in, const int* in_sizes, int n_in,
                              void* d_out, int out_size){
  (void)in_sizes; (void)n_in; (void)out_size;
  const float* x    = (const float*)d_in[0];
  const float* V    = (const float*)d_in[1];
  const float* U    = (const float*)d_in[2];
  const float* v2   = (const float*)d_in[3];
  const float* v1   = (const float*)d_in[4];
  const float* u2   = (const float*)d_in[5];
  const float* u1   = (const float*)d_in[6];
  const float* V_R  = (const float*)d_in[7];
  const float* U_R  = (const float*)d_in[8];
  const float* v2_R = (const float*)d_in[9];
  const float* v1_R = (const float*)d_in[10];
  const float* u2_R = (const float*)d_in[11];
  const float* u1_R = (const float*)d_in[12];
  const float* bias = (const float*)d_in[13];
  float* out = (float*)d_out;

  __half *xp, *cv, *cu, *hp; uint32_t *mv, *mu; float* s1;
  cudaGetSymbolAddress((void**)&xp, g_xp);
  cudaGetSymbolAddress((void**)&cv, g_cv);
  cudaGetSymbolAddress((void**)&cu, g_cu);
  cudaGetSymbolAddress((void**)&hp, g_hp);
  cudaGetSymbolAddress((void**)&mv, g_mv);
  cudaGetSymbolAddress((void**)&mu, g_mu);
  cudaGetSymbolAddress((void**)&s1, g_s1);

  prep_w_k<<<1025, 256>>>(V, U, v1, u2, u1, V_R, U_R, v1_R, u2_R, u1_R);
  prep_x_k<<<4096, 256>>>((const float4*)x, (const float4*)v2, (const float4*)v2_R);

  cudaFuncSetAttribute(spgemm_k<0>, cudaFuncAttributeMaxDynamicSharedMemorySize, SMEMB);
  cudaFuncSetAttribute(spgemm_k<1>, cudaFuncAttributeMaxDynamicSharedMemorySize, SMEMB);

  // GEMM1: weights = sgn(V) (per branch), B = x' -> H' (pair-transformed, s1-scaled)
  dim3 g1(8, 64, 2);   // wtiles(1024/128) x btiles(8192/128) x branch
  spgemm_k<0><<<g1, 128, SMEMB>>>(cv, mv, xp, 4096,
                                  1024ull*2048, 64ull*128*16, 8192ull*4096,
                                  s1, hp, nullptr);
  // GEMM2: weights = sgn(Ucat)*u1, B = H' -> out + bias
  dim3 g2(32, 64, 1);  // wtiles(4096/128) x btiles
  spgemm_k<1><<<g2, 128, SMEMB>>>(cu, mu, hp, 2048,
                                  0, 0, 0,
                                  bias, nullptr, out);
}

// round 15
// speedup vs baseline: 1.0115x; 1.0115x over previous
#include <cuda_runtime.h>
#include <cuda_fp16.h>
#include <cstdint>

// ---------------------------------------------------------------------------
// y = sum_b ((x*v2_b) @ sign(V_b)^T * (v1_b*u2_b)) @ sign(U_b)^T * u1_b + bias
// Binary +-1 weights -> exact 2:4 sparsity (pair transform), mma.sp
// ::ordered_metadata.m16n8k32, measured at its acceptance floor (~22.8
// cyc/instr/SMSP, invariant to occ/regs/smem). R14: R11 record config;
// cu/mu (G2 weight prep) folded into G1's launch as tail CTAs that fill
// G1's 3.46-wave quantization bubble. No .cs hints (R13 regression).
// ---------------------------------------------------------------------------

#define WTILE 128   // weight rows per CTA
#define XT 128      // batch cols per CTA
#define STG 3
#define AROWB 80    // compressed A row: 32 halfs (64B) padded to 80
#define BROWB 144   // B row: 64 halfs (128B) padded to 144
#define SPA (WTILE*AROWB)         // 10240
#define SPB (XT*BROWB)            // 18432
#define SPM 1024                  // meta per stage
#define STGB (SPA+SPB+SPM)        // 29696
#define SMEMB (STG*STGB)          // 89088

__device__ __align__(16) __half   g_xp[2ull*8192*4096];   // x' pairs per branch
__device__ __align__(16) __half   g_cv[2ull*1024*2048];   // compressed sgn(V)
__device__ __align__(16) __half   g_cu[4096ull*1024];     // compressed sgn(U)*u1 (concat)
__device__ __align__(16) __half   g_hp[8192ull*2048];     // H' pairs
__device__ __align__(16) uint32_t g_mv[2ull*64*128*16];   // metadata V (both branches)
__device__ __align__(16) uint32_t g_mu[256ull*64*16];     // metadata Ucat
__device__ float g_s1[2048];

__device__ __forceinline__ uint32_t smem_u32(const void* p){
  uint32_t a;
  asm("{ .reg .u64 t; cvta.to.shared.u64 t, %1; cvt.u32.u64 %0, t; }" : "=r"(a) : "l"(p));
  return a;
}
__device__ __forceinline__ void cp16(uint32_t dst, const void* src){
  asm volatile("cp.async.cg.shared.global [%0], [%1], 16;" :: "r"(dst), "l"(src));
}
__device__ __forceinline__ void cp8(uint32_t dst, const void* src){
  asm volatile("cp.async.ca.shared.global [%0], [%1], 8;" :: "r"(dst), "l"(src));
}
__device__ __forceinline__ void ldsm4(uint32_t& r0, uint32_t& r1, uint32_t& r2,
                                      uint32_t& r3, uint32_t addr){
  asm volatile("ldmatrix.sync.aligned.m8n8.x4.shared.b16 {%0,%1,%2,%3}, [%4];"
    : "=r"(r0), "=r"(r1), "=r"(r2), "=r"(r3) : "r"(addr));
}
__device__ __forceinline__ void mma_sp(float* d, const uint32_t* a,
                                       const uint32_t* b, uint32_t e){
  asm volatile("mma.sp::ordered_metadata.sync.aligned.m16n8k32.row.col.f32.f16.f16.f32 "
    "{%0,%1,%2,%3}, {%4,%5,%6,%7}, {%8,%9,%10,%11}, {%0,%1,%2,%3}, %12, 0x0;"
    : "+f"(d[0]), "+f"(d[1]), "+f"(d[2]), "+f"(d[3])
    : "r"(a[0]), "r"(a[1]), "r"(a[2]), "r"(a[3]),
      "r"(b[0]), "r"(b[1]), "r"(b[2]), "r"(b[3]), "r"(e));
}
__device__ __forceinline__ float sg(float v){ return v > 0.f ? 1.f : (v < 0.f ? -1.f : 0.f); }

// ------------------------------ prep: xp ------------------------------------
// x' pairs, float4 granularity. Lean streaming kernel, full occupancy.
__global__ void __launch_bounds__(256, 8)
prep_x_k(const float4* __restrict__ xv4, const float4* __restrict__ a4,
         const float4* __restrict__ b4){
  uint2* oA = reinterpret_cast<uint2*>(g_xp);
  uint2* oB = reinterpret_cast<uint2*>(g_xp + 8192ull*4096);
  const size_t n = 8192ull*1024;
  for (size_t i = (size_t)blockIdx.x*256 + threadIdx.x; i < n; i += 4096ull*256){
    float4 xv = xv4[i];
    int t = (int)(i & 1023);
    float4 a = a4[t], b = b4[t];
    float s0 = xv.x*a.x, s1 = xv.y*a.y, s2 = xv.z*a.z, s3 = xv.w*a.w;
    __half2 h0 = __floats2half2_rn(s0 + s1, s0 - s1);
    __half2 h1 = __floats2half2_rn(s2 + s3, s2 - s3);
    uint2 oa; oa.x = *reinterpret_cast<uint32_t*>(&h0);
    oa.y = *reinterpret_cast<uint32_t*>(&h1);
    oA[i] = oa;
    float r0 = xv.x*b.x, r1 = xv.y*b.y, r2 = xv.z*b.z, r3 = xv.w*b.w;
    h0 = __floats2half2_rn(r0 + r1, r0 - r1);
    h1 = __floats2half2_rn(r2 + r3, r2 - r3);
    uint2 ob; ob.x = *reinterpret_cast<uint32_t*>(&h0);
    ob.y = *reinterpret_cast<uint32_t*>(&h1);
    oB[i] = ob;
  }
}

// ---------------------------- prep: weights (V only + s1) -------------------
// sections by blockIdx.x:
//   [0,512)  cv+mv : compressed sgn(V/V_R) AND metadata from one V read
//   [512]    s1    : v1*u2 concat
// (cu/mu for G2 is produced by tail CTAs inside the G1 launch.)
__global__ void prep_w_k(const float* __restrict__ V,
                         const float* __restrict__ v1, const float* __restrict__ u2,
                         const float* __restrict__ VR,
                         const float* __restrict__ v1R, const float* __restrict__ u2R){
  const int bid = blockIdx.x, tid = threadIdx.x;
  if (bid < 512){
    const size_t half = 64ull*128*16;   // words per branch
    for (size_t i = (size_t)bid*256 + tid; i < 2*half; i += 512ull*256){
      int br = i >= half;
      size_t idx = br ? i - half : i;
      const float* W = br ? VR : V;
      int w = (int)(idx & 15), q = w >> 1, s = w & 1;
      size_t cw = idx >> 4;
      int c = (int)(cw & 127);
      int b = (int)(cw >> 7);
      int r0 = b*16 + q;
      int kb = c*32 + s*16;
      const float* p0 = W + (size_t)r0*4096 + kb;
      const float* p1 = p0 + (size_t)8*4096;
      uint32_t lo = 0, hi = 0;
      uint4 cv0, cv1;
      uint32_t* c0 = reinterpret_cast<uint32_t*>(&cv0);
      uint32_t* c1 = reinterpret_cast<uint32_t*>(&cv1);
      #pragma unroll
      for (int g = 0; g < 4; g++){
        float4 a = *(const float4*)(p0 + g*4);
        float4 bb = *(const float4*)(p1 + g*4);
        lo |= ((((a.x < 0.f) == (a.y < 0.f)) ? 0u : 1u)
             | ((((a.z < 0.f) == (a.w < 0.f)) ? 2u : 3u) << 2)) << (4*g);
        hi |= ((((bb.x < 0.f) == (bb.y < 0.f)) ? 0u : 1u)
             | ((((bb.z < 0.f) == (bb.w < 0.f)) ? 2u : 3u) << 2)) << (4*g);
        __half2 ha = __floats2half2_rn(sg(a.x), sg(a.z));
        __half2 hb = __floats2half2_rn(sg(bb.x), sg(bb.z));
        c0[g] = *reinterpret_cast<uint32_t*>(&ha);
        c1[g] = *reinterpret_cast<uint32_t*>(&hb);
      }
      g_mv[(br ? half : 0) + idx] = lo | (hi << 16);
      size_t cvbase = (size_t)br*1024*2048;
      int t0 = c*16 + s*8;
      *reinterpret_cast<uint4*>(g_cv + cvbase + (size_t)r0*2048 + t0)     = cv0;
      *reinterpret_cast<uint4*>(g_cv + cvbase + (size_t)(r0+8)*2048 + t0) = cv1;
    }
  } else {
    for (int j = tid; j < 1024; j += 256){
      g_s1[j] = v1[j]*u2[j];
      g_s1[1024+j] = v1R[j]*u2R[j];
    }
  }
}

// --------------------------- sparse GEMM kernel -----------------------------
// R11 record shape. D[w, b] = Wsp[w, Klog] (2:4) @ X'[b, Klog]^T.
// MODE 0: H' = pairTransform(D * s1) fp16; tail CTAs (blockIdx.y >= 64)
//         instead produce cu/mu (G2 weights) and retire into G1's wave bubble.
// MODE 1: out[b][w] = D + bias[w].
template<int MODE>
__global__ void __launch_bounds__(128, 2)
spgemm_k(const __half* __restrict__ Ac, const uint32_t* __restrict__ Mt,
         const __half* __restrict__ Bx, int Klog,
         size_t strideAc, size_t strideMt, size_t strideBx,
         const float* __restrict__ aux, __half* __restrict__ outH,
         float* __restrict__ outF,
         const float* __restrict__ Uw, const float* __restrict__ URw,
         const float* __restrict__ u1w, const float* __restrict__ u1Rw)
{
  extern __shared__ char smem[];
  const uint32_t sb = smem_u32(smem);
  const int tid = threadIdx.x, wid = tid >> 5, lane = tid & 31;
  const int wt = blockIdx.x, bt = blockIdx.y, bz = blockIdx.z;

  if (MODE == 0 && bt >= 64){
    // ---- embedded cu+mu prep (for GEMM2), grid-stride over meta words ----
    const size_t n = 256ull*64*16;
    size_t t0 = ((((size_t)bz*16 + (bt - 64))*8 + wt)*128) + tid;  // 32768 threads
    for (size_t idx = t0; idx < n; idx += 32768){
      int w = (int)(idx & 15), q = w >> 1, s = w & 1;
      size_t cw = idx >> 4;
      int c = (int)(cw & 63);
      int b = (int)(cw >> 6);
      int r0 = b*16 + q;
      int kb = c*32 + s*16;
      const float* W   = (kb < 1024) ? Uw  : URw;
      const float* u1v = (kb < 1024) ? u1w : u1Rw;
      int coff = (kb < 1024) ? kb : kb - 1024;
      const float* p0 = W + (size_t)r0*1024 + coff;
      const float* p1 = p0 + (size_t)8*1024;
      float sc0 = u1v[r0], sc1 = u1v[r0+8];
      uint32_t lo = 0, hi = 0;
      uint4 cv0, cv1;
      uint32_t* c0 = reinterpret_cast<uint32_t*>(&cv0);
      uint32_t* c1 = reinterpret_cast<uint32_t*>(&cv1);
      #pragma unroll
      for (int g = 0; g < 4; g++){
        float4 a = *(const float4*)(p0 + g*4);
        float4 bb = *(const float4*)(p1 + g*4);
        lo |= ((((a.x < 0.f) == (a.y < 0.f)) ? 0u : 1u)
             | ((((a.z < 0.f) == (a.w < 0.f)) ? 2u : 3u) << 2)) << (4*g);
        hi |= ((((bb.x < 0.f) == (bb.y < 0.f)) ? 0u : 1u)
             | ((((bb.z < 0.f) == (bb.w < 0.f)) ? 2u : 3u) << 2)) << (4*g);
        __half2 ha = __floats2half2_rn(sg(a.x)*sc0, sg(a.z)*sc0);
        __half2 hb = __floats2half2_rn(sg(bb.x)*sc1, sg(bb.z)*sc1);
        c0[g] = *reinterpret_cast<uint32_t*>(&ha);
        c1[g] = *reinterpret_cast<uint32_t*>(&hb);
      }
      g_mu[idx] = lo | (hi << 16);
      int t0c = c*16 + s*8;
      *reinterpret_cast<uint4*>(g_cu + (size_t)r0*1024 + t0c)     = cv0;
      *reinterpret_cast<uint4*>(g_cu + (size_t)(r0+8)*1024 + t0c) = cv1;
    }
    return;
  }

  const int ww = wid >> 1, wb = wid & 1;   // weights ww*64.., batch wb*64..
  const int Kc = Klog >> 1;
  const int chunks = Klog >> 5;
  const __half* Acb = Ac + strideAc*bz + (size_t)wt*WTILE*Kc;
  const uint32_t* Mtb = Mt + strideMt*bz + (size_t)(wt*8)*chunks*16;
  const __half* Bxb = Bx + strideBx*bz + (size_t)bt*XT*Klog;
  const int KS = Klog / 64;

  #define LOAD_STAGE(buf, ks_) do {                                           \
    uint32_t st_ = sb + (buf)*STGB;                                           \
    uint32_t as_ = st_, bs_ = st_ + SPA, ms_ = st_ + SPA + SPB;               \
    _Pragma("unroll")                                                         \
    for (int i_ = 0; i_ < 4; i_++){                                           \
      int idx_ = tid + i_*128, r_ = idx_ >> 2, c_ = idx_ & 3;                 \
      cp16(as_ + r_*AROWB + c_*16, Acb + (size_t)r_*Kc + (ks_)*32 + c_*8);    \
    }                                                                         \
    _Pragma("unroll")                                                         \
    for (int i_ = 0; i_ < 8; i_++){                                           \
      int idx_ = tid + i_*128, r_ = idx_ >> 3, c_ = idx_ & 7;                 \
      cp16(bs_ + r_*BROWB + c_*16, Bxb + (size_t)r_*Klog + (ks_)*64 + c_*8);  \
    }                                                                         \
    { int f_ = tid*2, b_ = f_ >> 5, rem_ = f_ & 31;                           \
      int h_ = rem_ >> 4, w_ = rem_ & 15;                                     \
      cp8(ms_ + b_*128 + h_*64 + w_*4,                                        \
          Mtb + ((size_t)b_*chunks + 2*(ks_) + h_)*16 + w_); }                \
    asm volatile("cp.async.commit_group;" ::: "memory");                      \
  } while(0)

  LOAD_STAGE(0, 0);
  LOAD_STAGE(1, 1);

  float acc[4][8][4];
  #pragma unroll
  for (int i = 0; i < 4; i++)
    #pragma unroll
    for (int j = 0; j < 8; j++)
      #pragma unroll
      for (int k = 0; k < 4; k++) acc[i][j][k] = 0.f;

  const int l15 = lane & 15, l16 = lane >> 4;
  const uint32_t eOff = ((((lane >> 2) << 1) | (lane & 1)) << 2);
  int stage = 0;

  for (int ks = 0; ks < KS; ks++){
    asm volatile("cp.async.wait_group %0;" :: "n"(STG-2) : "memory");
    __syncthreads();
    if (ks + STG - 1 < KS){
      int nb = stage + (STG - 1); if (nb >= STG) nb -= STG;
      LOAD_STAGE(nb, ks + STG - 1);
    } else {
      asm volatile("cp.async.commit_group;" ::: "memory");
    }

    const uint32_t st = sb + stage*STGB;
    const uint32_t as = st, bs2 = st + SPA, ms = st + SPA + SPB;

    #pragma unroll
    for (int h = 0; h < 2; h++){
      uint32_t af[4][4], ev[4], bf[8][4];
      #pragma unroll
      for (int i = 0; i < 4; i++){
        ldsm4(af[i][0], af[i][1], af[i][2], af[i][3],
              as + (uint32_t)((ww*64 + i*16 + l15)*AROWB) + l16*16 + h*32);
        asm volatile("ld.shared.b32 %0, [%1];" : "=r"(ev[i])
          : "r"(ms + (uint32_t)((ww*4 + i)*128 + h*64) + eOff));
      }
      #pragma unroll
      for (int j = 0; j < 4; j++){
        #pragma unroll
        for (int kh = 0; kh < 2; kh++){
          uint32_t t0, t1, t2, t3;
          ldsm4(t0, t1, t2, t3,
                bs2 + (uint32_t)((wb*64 + j*16 + l15)*BROWB) + l16*16 + h*64 + kh*32);
          bf[j*2+0][kh*2+0] = t0; bf[j*2+0][kh*2+1] = t2;
          bf[j*2+1][kh*2+0] = t1; bf[j*2+1][kh*2+1] = t3;
        }
      }
      #pragma unroll
      for (int i = 0; i < 4; i++)
        #pragma unroll
        for (int j = 0; j < 8; j++)
          mma_sp(acc[i][j], af[i], bf[j], ev[i]);
    }
    if (++stage == STG) stage = 0;
  }

  asm volatile("cp.async.wait_group 0;" ::: "memory");
  __syncthreads();

  // ----------------------------- epilogue -----------------------------------
  const int qr = lane >> 2;
  const int qc = (lane & 3) * 2;

  if (MODE == 0){
    const uint32_t epi = sb + wid*8448;     // 64 x (66 halfs)
    const int jgBase = bz*1024 + wt*128 + ww*64;
    #pragma unroll
    for (int mf = 0; mf < 4; mf++){
      float sA = aux[jgBase + mf*16 + qr];
      float sB = aux[jgBase + mf*16 + qr + 8];
      #pragma unroll
      for (int nf = 0; nf < 8; nf++){
        float v0 = acc[mf][nf][0]*sA, v1 = acc[mf][nf][1]*sA;
        float v2 = acc[mf][nf][2]*sB, v3 = acc[mf][nf][3]*sB;
        float p0 = __shfl_xor_sync(0xffffffffu, v0, 4);
        float p1 = __shfl_xor_sync(0xffffffffu, v1, 4);
        float p2 = __shfl_xor_sync(0xffffffffu, v2, 4);
        float p3 = __shfl_xor_sync(0xffffffffu, v3, 4);
        bool even = (qr & 1) == 0;
        float r0 = even ? v0 + p0 : p0 - v0;
        float r1 = even ? v1 + p1 : p1 - v1;
        float r2 = even ? v2 + p2 : p2 - v2;
        float r3 = even ? v3 + p3 : p3 - v3;
        int bc = nf*8 + qc, jl = mf*16 + qr;
        uint32_t a0 = epi + (uint32_t)(bc*132 + jl*2);
        uint32_t a1 = epi + (uint32_t)((bc+1)*132 + jl*2);
        __half h0 = __float2half_rn(r0), h1 = __float2half_rn(r1);
        __half h2 = __float2half_rn(r2), h3 = __float2half_rn(r3);
        asm volatile("st.shared.b16 [%0], %1;" :: "r"(a0),      "h"(*(uint16_t*)&h0));
        asm volatile("st.shared.b16 [%0], %1;" :: "r"(a1),      "h"(*(uint16_t*)&h1));
        asm volatile("st.shared.b16 [%0], %1;" :: "r"(a0 + 16), "h"(*(uint16_t*)&h2));
        asm volatile("st.shared.b16 [%0], %1;" :: "r"(a1 + 16), "h"(*(uint16_t*)&h3));
      }
    }
    __syncwarp();
    const int colg = bz*1024 + wt*128 + ww*64 + lane*2;
    #pragma unroll 4
    for (int rb = 0; rb < 64; rb++){
      uint32_t v;
      asm volatile("ld.shared.b32 %0, [%1];" : "=r"(v) : "r"(epi + (uint32_t)(rb*132 + lane*4)));
      *reinterpret_cast<uint32_t*>(outH + (size_t)(bt*128 + wb*64 + rb)*2048 + colg) = v;
    }
  } else {
    const uint32_t epi = sb + wid*16896;    // 64 x (66 floats)
    #pragma unroll
    for (int mf = 0; mf < 4; mf++){
      #pragma unroll
      for (int nf = 0; nf < 8; nf++){
        int bc = nf*8 + qc, jl = mf*16 + qr;
        uint32_t a0 = epi + (uint32_t)(bc*264 + jl*4);
        uint32_t a1 = epi + (uint32_t)((bc+1)*264 + jl*4);
        asm volatile("st.shared.f32 [%0], %1;" :: "r"(a0),      "f"(acc[mf][nf][0]));
        asm volatile("st.shared.f32 [%0], %1;" :: "r"(a1),      "f"(acc[mf][nf][1]));
        asm volatile("st.shared.f32 [%0], %1;" :: "r"(a0 + 32), "f"(acc[mf][nf][2]));
        asm volatile("st.shared.f32 [%0], %1;" :: "r"(a1 + 32), "f"(acc[mf][nf][3]));
      }
    }
    __syncwarp();
    const int c0 = wt*128 + ww*64 + lane*2;
    float2 bb = *reinterpret_cast<const float2*>(aux + c0);
    #pragma unroll 4
    for (int rb = 0; rb < 64; rb++){
      float2 v;
      asm volatile("ld.shared.v2.f32 {%0,%1}, [%2];" : "=f"(v.x), "=f"(v.y)
        : "r"(epi + (uint32_t)(rb*264 + lane*8)));
      v.x += bb.x; v.y += bb.y;
      *reinterpret_cast<float2*>(outF + (size_t)(bt*128 + wb*64 + rb)*4096 + c0) = v;
    }
  }
  #undef LOAD_STAGE
}

// ----------------------------- launch ---------------------------------------
extern "C" void kernel_launch(void* const* d_in, const int* in_sizes, int n_in,
                              void* d_out, int out_size){
  (void)in_sizes; (void)n_in; (void)out_size;
  const float* x    = (const float*)d_in[0];
  const float* V    = (const float*)d_in[1];
  const float* U    = (const float*)d_in[2];
  const float* v2   = (const float*)d_in[3];
  const float* v1   = (const float*)d_in[4];
  const float* u2   = (const float*)d_in[5];
  const float* u1   = (const float*)d_in[6];
  const float* V_R  = (const float*)d_in[7];
  const float* U_R  = (const float*)d_in[8];
  const float* v2_R = (const float*)d_in[9];
  const float* v1_R = (const float*)d_in[10];
  const float* u2_R = (const float*)d_in[11];
  const float* u1_R = (const float*)d_in[12];
  const float* bias = (const float*)d_in[13];
  float* out = (float*)d_out;

  __half *xp, *cv, *cu, *hp; uint32_t *mv, *mu; float* s1;
  cudaGetSymbolAddress((void**)&xp, g_xp);
  cudaGetSymbolAddress((void**)&cv, g_cv);
  cudaGetSymbolAddress((void**)&cu, g_cu);
  cudaGetSymbolAddress((void**)&hp, g_hp);
  cudaGetSymbolAddress((void**)&mv, g_mv);
  cudaGetSymbolAddress((void**)&mu, g_mu);
  cudaGetSymbolAddress((void**)&s1, g_s1);

  prep_w_k<<<513, 256>>>(V, v1, u2, V_R, v1_R, u2_R);
  prep_x_k<<<4096, 256>>>((const float4*)x, (const float4*)v2, (const float4*)v2_R);

  cudaFuncSetAttribute(spgemm_k<0>, cudaFuncAttributeMaxDynamicSharedMemorySize, SMEMB);
  cudaFuncSetAttribute(spgemm_k<1>, cudaFuncAttributeMaxDynamicSharedMemorySize, SMEMB);

  // GEMM1 (+ embedded cu/mu prep in tail CTAs, y in [64,80)):
  dim3 g1(8, 80, 2);   // wtiles x (btiles 64 | prep 16) x branch
  spgemm_k<0><<<g1, 128, SMEMB>>>(cv, mv, xp, 4096,
                                  1024ull*2048, 64ull*128*16, 8192ull*4096,
                                  s1, hp, nullptr,
                                  U, U_R, u1, u1_R);
  // GEMM2: weights = sgn(Ucat)*u1, B = H' -> out + bias
  dim3 g2(32, 64, 1);  // wtiles(4096/128) x btiles
  spgemm_k<1><<<g2, 128, SMEMB>>>(cu, mu, hp, 2048,
                                  0, 0, 0,
                                  bias, nullptr, out,
                                  nullptr, nullptr, nullptr, nullptr);
}

// round 16
// speedup vs baseline: 1.0132x; 1.0016x over previous
#include <cuda_runtime.h>
#include <cuda_fp16.h>
#include <cstdint>

// ---------------------------------------------------------------------------
// y = sum_b ((x*v2_b) @ sign(V_b)^T * (v1_b*u2_b)) @ sign(U_b)^T * u1_b + bias
// Binary +-1 weights -> exact 2:4 sparsity (pair transform), mma.sp
// ::ordered_metadata.m16n8k32 at its acceptance floor (~22.8 cyc/instr/SMSP,
// invariant). R15: single merged prep launch (xp ILP2 + cv/mv + s1) under
// launch_bounds(256,8) so the streaming section keeps full occupancy (weight
// section spills a little); cu/mu still embedded in G1's tail CTAs. 3 launches.
// ---------------------------------------------------------------------------

#define WTILE 128   // weight rows per CTA
#define XT 128      // batch cols per CTA
#define STG 3
#define AROWB 80    // compressed A row: 32 halfs (64B) padded to 80
#define BROWB 144   // B row: 64 halfs (128B) padded to 144
#define SPA (WTILE*AROWB)         // 10240
#define SPB (XT*BROWB)            // 18432
#define SPM 1024                  // meta per stage
#define STGB (SPA+SPB+SPM)        // 29696
#define SMEMB (STG*STGB)          // 89088

__device__ __align__(16) __half   g_xp[2ull*8192*4096];   // x' pairs per branch
__device__ __align__(16) __half   g_cv[2ull*1024*2048];   // compressed sgn(V)
__device__ __align__(16) __half   g_cu[4096ull*1024];     // compressed sgn(U)*u1 (concat)
__device__ __align__(16) __half   g_hp[8192ull*2048];     // H' pairs
__device__ __align__(16) uint32_t g_mv[2ull*64*128*16];   // metadata V (both branches)
__device__ __align__(16) uint32_t g_mu[256ull*64*16];     // metadata Ucat
__device__ float g_s1[2048];

__device__ __forceinline__ uint32_t smem_u32(const void* p){
  uint32_t a;
  asm("{ .reg .u64 t; cvta.to.shared.u64 t, %1; cvt.u32.u64 %0, t; }" : "=r"(a) : "l"(p));
  return a;
}
__device__ __forceinline__ void cp16(uint32_t dst, const void* src){
  asm volatile("cp.async.cg.shared.global [%0], [%1], 16;" :: "r"(dst), "l"(src));
}
__device__ __forceinline__ void cp8(uint32_t dst, const void* src){
  asm volatile("cp.async.ca.shared.global [%0], [%1], 8;" :: "r"(dst), "l"(src));
}
__device__ __forceinline__ void ldsm4(uint32_t& r0, uint32_t& r1, uint32_t& r2,
                                      uint32_t& r3, uint32_t addr){
  asm volatile("ldmatrix.sync.aligned.m8n8.x4.shared.b16 {%0,%1,%2,%3}, [%4];"
    : "=r"(r0), "=r"(r1), "=r"(r2), "=r"(r3) : "r"(addr));
}
__device__ __forceinline__ void mma_sp(float* d, const uint32_t* a,
                                       const uint32_t* b, uint32_t e){
  asm volatile("mma.sp::ordered_metadata.sync.aligned.m16n8k32.row.col.f32.f16.f16.f32 "
    "{%0,%1,%2,%3}, {%4,%5,%6,%7}, {%8,%9,%10,%11}, {%0,%1,%2,%3}, %12, 0x0;"
    : "+f"(d[0]), "+f"(d[1]), "+f"(d[2]), "+f"(d[3])
    : "r"(a[0]), "r"(a[1]), "r"(a[2]), "r"(a[3]),
      "r"(b[0]), "r"(b[1]), "r"(b[2]), "r"(b[3]), "r"(e));
}
__device__ __forceinline__ float sg(float v){ return v > 0.f ? 1.f : (v < 0.f ? -1.f : 0.f); }

// ------------------------- merged prep (ONE launch) -------------------------
// sections by blockIdx.x:
//   [0,4096)     xp    : x' pair transform, both branches, 2-way ILP
//   [4096,4608)  cv+mv : compressed sgn(V/V_R) AND metadata from one V read
//   [4608]       s1    : v1*u2 concat
// launch_bounds(256,8): streaming xp section keeps full occupancy; the small
// weight section may spill a few regs (bounded, ~7us of work total).
#define PREP_BLOCKS 4609

__global__ void __launch_bounds__(256, 8)
prep_all_k(const float4* __restrict__ xv4, const float4* __restrict__ a4,
           const float4* __restrict__ b4,
           const float* __restrict__ V,  const float* __restrict__ VR,
           const float* __restrict__ v1, const float* __restrict__ u2,
           const float* __restrict__ v1R, const float* __restrict__ u2R){
  const int bid = blockIdx.x, tid = threadIdx.x;
  if (bid < 4096){
    // ---- x' pairs, float4 granularity, 2-way ILP (no cache hints) ----
    uint2* oA = reinterpret_cast<uint2*>(g_xp);
    uint2* oB = reinterpret_cast<uint2*>(g_xp + 8192ull*4096);
    const size_t n = 8192ull*1024;
    const size_t stride = 4096ull*256;
    for (size_t i = (size_t)bid*256 + tid; i < n; i += 2*stride){
      size_t j = i + stride;
      float4 xv0 = xv4[i];
      float4 xv1 = (j < n) ? xv4[j] : make_float4(0.f,0.f,0.f,0.f);
      {
        int t = (int)(i & 1023);
        float4 a = a4[t], b = b4[t];
        float s0 = xv0.x*a.x, s1 = xv0.y*a.y, s2 = xv0.z*a.z, s3 = xv0.w*a.w;
        __half2 h0 = __floats2half2_rn(s0 + s1, s0 - s1);
        __half2 h1 = __floats2half2_rn(s2 + s3, s2 - s3);
        uint2 oa; oa.x = *reinterpret_cast<uint32_t*>(&h0);
        oa.y = *reinterpret_cast<uint32_t*>(&h1);
        oA[i] = oa;
        float r0 = xv0.x*b.x, r1 = xv0.y*b.y, r2 = xv0.z*b.z, r3 = xv0.w*b.w;
        h0 = __floats2half2_rn(r0 + r1, r0 - r1);
        h1 = __floats2half2_rn(r2 + r3, r2 - r3);
        uint2 ob; ob.x = *reinterpret_cast<uint32_t*>(&h0);
        ob.y = *reinterpret_cast<uint32_t*>(&h1);
        oB[i] = ob;
      }
      if (j < n){
        int t = (int)(j & 1023);
        float4 a = a4[t], b = b4[t];
        float s0 = xv1.x*a.x, s1 = xv1.y*a.y, s2 = xv1.z*a.z, s3 = xv1.w*a.w;
        __half2 h0 = __floats2half2_rn(s0 + s1, s0 - s1);
        __half2 h1 = __floats2half2_rn(s2 + s3, s2 - s3);
        uint2 oa; oa.x = *reinterpret_cast<uint32_t*>(&h0);
        oa.y = *reinterpret_cast<uint32_t*>(&h1);
        oA[j] = oa;
        float r0 = xv1.x*b.x, r1 = xv1.y*b.y, r2 = xv1.z*b.z, r3 = xv1.w*b.w;
        h0 = __floats2half2_rn(r0 + r1, r0 - r1);
        h1 = __floats2half2_rn(r2 + r3, r2 - r3);
        uint2 ob; ob.x = *reinterpret_cast<uint32_t*>(&h0);
        ob.y = *reinterpret_cast<uint32_t*>(&h1);
        oB[j] = ob;
      }
    }
  } else if (bid < 4608){
    // ---- cv + mv merged: per word, rows (r0, r0+8), k in [kb, kb+16) ----
    const size_t half = 64ull*128*16;   // words per branch
    for (size_t i = (size_t)(bid-4096)*256 + tid; i < 2*half; i += 512ull*256){
      int br = i >= half;
      size_t idx = br ? i - half : i;
      const float* W = br ? VR : V;
      int w = (int)(idx & 15), q = w >> 1, s = w & 1;
      size_t cw = idx >> 4;
      int c = (int)(cw & 127);
      int b = (int)(cw >> 7);
      int r0 = b*16 + q;
      int kb = c*32 + s*16;
      const float* p0 = W + (size_t)r0*4096 + kb;
      const float* p1 = p0 + (size_t)8*4096;
      uint32_t lo = 0, hi = 0;
      uint4 cv0, cv1;
      uint32_t* c0 = reinterpret_cast<uint32_t*>(&cv0);
      uint32_t* c1 = reinterpret_cast<uint32_t*>(&cv1);
      #pragma unroll
      for (int g = 0; g < 4; g++){
        float4 a = *(const float4*)(p0 + g*4);
        float4 bb = *(const float4*)(p1 + g*4);
        lo |= ((((a.x < 0.f) == (a.y < 0.f)) ? 0u : 1u)
             | ((((a.z < 0.f) == (a.w < 0.f)) ? 2u : 3u) << 2)) << (4*g);
        hi |= ((((bb.x < 0.f) == (bb.y < 0.f)) ? 0u : 1u)
             | ((((bb.z < 0.f) == (bb.w < 0.f)) ? 2u : 3u) << 2)) << (4*g);
        __half2 ha = __floats2half2_rn(sg(a.x), sg(a.z));
        __half2 hb = __floats2half2_rn(sg(bb.x), sg(bb.z));
        c0[g] = *reinterpret_cast<uint32_t*>(&ha);
        c1[g] = *reinterpret_cast<uint32_t*>(&hb);
      }
      g_mv[(br ? half : 0) + idx] = lo | (hi << 16);
      size_t cvbase = (size_t)br*1024*2048;
      int t0 = c*16 + s*8;
      *reinterpret_cast<uint4*>(g_cv + cvbase + (size_t)r0*2048 + t0)     = cv0;
      *reinterpret_cast<uint4*>(g_cv + cvbase + (size_t)(r0+8)*2048 + t0) = cv1;
    }
  } else {
    for (int j = tid; j < 1024; j += 256){
      g_s1[j] = v1[j]*u2[j];
      g_s1[1024+j] = v1R[j]*u2R[j];
    }
  }
}

// --------------------------- sparse GEMM kernel -----------------------------
// R11 record shape. D[w, b] = Wsp[w, Klog] (2:4) @ X'[b, Klog]^T.
// MODE 0: H' = pairTransform(D * s1) fp16; tail CTAs (blockIdx.y >= 64)
//         instead produce cu/mu (G2 weights) and retire into G1's wave bubble.
// MODE 1: out[b][w] = D + bias[w].
template<int MODE>
__global__ void __launch_bounds__(128, 2)
spgemm_k(const __half* __restrict__ Ac, const uint32_t* __restrict__ Mt,
         const __half* __restrict__ Bx, int Klog,
         size_t strideAc, size_t strideMt, size_t strideBx,
         const float* __restrict__ aux, __half* __restrict__ outH,
         float* __restrict__ outF,
         const float* __restrict__ Uw, const float* __restrict__ URw,
         const float* __restrict__ u1w, const float* __restrict__ u1Rw)
{
  extern __shared__ char smem[];
  const uint32_t sb = smem_u32(smem);
  const int tid = threadIdx.x, wid = tid >> 5, lane = tid & 31;
  const int wt = blockIdx.x, bt = blockIdx.y, bz = blockIdx.z;

  if (MODE == 0 && bt >= 64){
    // ---- embedded cu+mu prep (for GEMM2), grid-stride over meta words ----
    const size_t n = 256ull*64*16;
    size_t t0 = ((((size_t)bz*16 + (bt - 64))*8 + wt)*128) + tid;  // 32768 threads
    for (size_t idx = t0; idx < n; idx += 32768){
      int w = (int)(idx & 15), q = w >> 1, s = w & 1;
      size_t cw = idx >> 4;
      int c = (int)(cw & 63);
      int b = (int)(cw >> 6);
      int r0 = b*16 + q;
      int kb = c*32 + s*16;
      const float* W   = (kb < 1024) ? Uw  : URw;
      const float* u1v = (kb < 1024) ? u1w : u1Rw;
      int coff = (kb < 1024) ? kb : kb - 1024;
      const float* p0 = W + (size_t)r0*1024 + coff;
      const float* p1 = p0 + (size_t)8*1024;
      float sc0 = u1v[r0], sc1 = u1v[r0+8];
      uint32_t lo = 0, hi = 0;
      uint4 cv0, cv1;
      uint32_t* c0 = reinterpret_cast<uint32_t*>(&cv0);
      uint32_t* c1 = reinterpret_cast<uint32_t*>(&cv1);
      #pragma unroll
      for (int g = 0; g < 4; g++){
        float4 a = *(const float4*)(p0 + g*4);
        float4 bb = *(const float4*)(p1 + g*4);
        lo |= ((((a.x < 0.f) == (a.y < 0.f)) ? 0u : 1u)
             | ((((a.z < 0.f) == (a.w < 0.f)) ? 2u : 3u) << 2)) << (4*g);
        hi |= ((((bb.x < 0.f) == (bb.y < 0.f)) ? 0u : 1u)
             | ((((bb.z < 0.f) == (bb.w < 0.f)) ? 2u : 3u) << 2)) << (4*g);
        __half2 ha = __floats2half2_rn(sg(a.x)*sc0, sg(a.z)*sc0);
        __half2 hb = __floats2half2_rn(sg(bb.x)*sc1, sg(bb.z)*sc1);
        c0[g] = *reinterpret_cast<uint32_t*>(&ha);
        c1[g] = *reinterpret_cast<uint32_t*>(&hb);
      }
      g_mu[idx] = lo | (hi << 16);
      int t0c = c*16 + s*8;
      *reinterpret_cast<uint4*>(g_cu + (size_t)r0*1024 + t0c)     = cv0;
      *reinterpret_cast<uint4*>(g_cu + (size_t)(r0+8)*1024 + t0c) = cv1;
    }
    return;
  }

  const int ww = wid >> 1, wb = wid & 1;   // weights ww*64.., batch wb*64..
  const int Kc = Klog >> 1;
  const int chunks = Klog >> 5;
  const __half* Acb = Ac + strideAc*bz + (size_t)wt*WTILE*Kc;
  const uint32_t* Mtb = Mt + strideMt*bz + (size_t)(wt*8)*chunks*16;
  const __half* Bxb = Bx + strideBx*bz + (size_t)bt*XT*Klog;
  const int KS = Klog / 64;

  #define LOAD_STAGE(buf, ks_) do {                                           \
    uint32_t st_ = sb + (buf)*STGB;                                           \
    uint32_t as_ = st_, bs_ = st_ + SPA, ms_ = st_ + SPA + SPB;               \
    _Pragma("unroll")                                                         \
    for (int i_ = 0; i_ < 4; i_++){                                           \
      int idx_ = tid + i_*128, r_ = idx_ >> 2, c_ = idx_ & 3;                 \
      cp16(as_ + r_*AROWB + c_*16, Acb + (size_t)r_*Kc + (ks_)*32 + c_*8);    \
    }                                                                         \
    _Pragma("unroll")                                                         \
    for (int i_ = 0; i_ < 8; i_++){                                           \
      int idx_ = tid + i_*128, r_ = idx_ >> 3, c_ = idx_ & 7;                 \
      cp16(bs_ + r_*BROWB + c_*16, Bxb + (size_t)r_*Klog + (ks_)*64 + c_*8);  \
    }                                                                         \
    { int f_ = tid*2, b_ = f_ >> 5, rem_ = f_ & 31;                           \
      int h_ = rem_ >> 4, w_ = rem_ & 15;                                     \
      cp8(ms_ + b_*128 + h_*64 + w_*4,                                        \
          Mtb + ((size_t)b_*chunks + 2*(ks_) + h_)*16 + w_); }                \
    asm volatile("cp.async.commit_group;" ::: "memory");                      \
  } while(0)

  LOAD_STAGE(0, 0);
  LOAD_STAGE(1, 1);

  float acc[4][8][4];
  #pragma unroll
  for (int i = 0; i < 4; i++)
    #pragma unroll
    for (int j = 0; j < 8; j++)
      #pragma unroll
      for (int k = 0; k < 4; k++) acc[i][j][k] = 0.f;

  const int l15 = lane & 15, l16 = lane >> 4;
  const uint32_t eOff = ((((lane >> 2) << 1) | (lane & 1)) << 2);
  int stage = 0;

  for (int ks = 0; ks < KS; ks++){
    asm volatile("cp.async.wait_group %0;" :: "n"(STG-2) : "memory");
    __syncthreads();
    if (ks + STG - 1 < KS){
      int nb = stage + (STG - 1); if (nb >= STG) nb -= STG;
      LOAD_STAGE(nb, ks + STG - 1);
    } else {
      asm volatile("cp.async.commit_group;" ::: "memory");
    }

    const uint32_t st = sb + stage*STGB;
    const uint32_t as = st, bs2 = st + SPA, ms = st + SPA + SPB;

    #pragma unroll
    for (int h = 0; h < 2; h++){
      uint32_t af[4][4], ev[4], bf[8][4];
      #pragma unroll
      for (int i = 0; i < 4; i++){
        ldsm4(af[i][0], af[i][1], af[i][2], af[i][3],
              as + (uint32_t)((ww*64 + i*16 + l15)*AROWB) + l16*16 + h*32);
        asm volatile("ld.shared.b32 %0, [%1];" : "=r"(ev[i])
          : "r"(ms + (uint32_t)((ww*4 + i)*128 + h*64) + eOff));
      }
      #pragma unroll
      for (int j = 0; j < 4; j++){
        #pragma unroll
        for (int kh = 0; kh < 2; kh++){
          uint32_t t0, t1, t2, t3;
          ldsm4(t0, t1, t2, t3,
                bs2 + (uint32_t)((wb*64 + j*16 + l15)*BROWB) + l16*16 + h*64 + kh*32);
          bf[j*2+0][kh*2+0] = t0; bf[j*2+0][kh*2+1] = t2;
          bf[j*2+1][kh*2+0] = t1; bf[j*2+1][kh*2+1] = t3;
        }
      }
      #pragma unroll
      for (int i = 0; i < 4; i++)
        #pragma unroll
        for (int j = 0; j < 8; j++)
          mma_sp(acc[i][j], af[i], bf[j], ev[i]);
    }
    if (++stage == STG) stage = 0;
  }

  asm volatile("cp.async.wait_group 0;" ::: "memory");
  __syncthreads();

  // ----------------------------- epilogue -----------------------------------
  const int qr = lane >> 2;
  const int qc = (lane & 3) * 2;

  if (MODE == 0){
    const uint32_t epi = sb + wid*8448;     // 64 x (66 halfs)
    const int jgBase = bz*1024 + wt*128 + ww*64;
    #pragma unroll
    for (int mf = 0; mf < 4; mf++){
      float sA = aux[jgBase + mf*16 + qr];
      float sB = aux[jgBase + mf*16 + qr + 8];
      #pragma unroll
      for (int nf = 0; nf < 8; nf++){
        float v0 = acc[mf][nf][0]*sA, v1 = acc[mf][nf][1]*sA;
        float v2 = acc[mf][nf][2]*sB, v3 = acc[mf][nf][3]*sB;
        float p0 = __shfl_xor_sync(0xffffffffu, v0, 4);
        float p1 = __shfl_xor_sync(0xffffffffu, v1, 4);
        float p2 = __shfl_xor_sync(0xffffffffu, v2, 4);
        float p3 = __shfl_xor_sync(0xffffffffu, v3, 4);
        bool even = (qr & 1) == 0;
        float r0 = even ? v0 + p0 : p0 - v0;
        float r1 = even ? v1 + p1 : p1 - v1;
        float r2 = even ? v2 + p2 : p2 - v2;
        float r3 = even ? v3 + p3 : p3 - v3;
        int bc = nf*8 + qc, jl = mf*16 + qr;
        uint32_t a0 = epi + (uint32_t)(bc*132 + jl*2);
        uint32_t a1 = epi + (uint32_t)((bc+1)*132 + jl*2);
        __half h0 = __float2half_rn(r0), h1 = __float2half_rn(r1);
        __half h2 = __float2half_rn(r2), h3 = __float2half_rn(r3);
        asm volatile("st.shared.b16 [%0], %1;" :: "r"(a0),      "h"(*(uint16_t*)&h0));
        asm volatile("st.shared.b16 [%0], %1;" :: "r"(a1),      "h"(*(uint16_t*)&h1));
        asm volatile("st.shared.b16 [%0], %1;" :: "r"(a0 + 16), "h"(*(uint16_t*)&h2));
        asm volatile("st.shared.b16 [%0], %1;" :: "r"(a1 + 16), "h"(*(uint16_t*)&h3));
      }
    }
    __syncwarp();
    const int colg = bz*1024 + wt*128 + ww*64 + lane*2;
    #pragma unroll 4
    for (int rb = 0; rb < 64; rb++){
      uint32_t v;
      asm volatile("ld.shared.b32 %0, [%1];" : "=r"(v) : "r"(epi + (uint32_t)(rb*132 + lane*4)));
      *reinterpret_cast<uint32_t*>(outH + (size_t)(bt*128 + wb*64 + rb)*2048 + colg) = v;
    }
  } else {
    const uint32_t epi = sb + wid*16896;    // 64 x (66 floats)
    #pragma unroll
    for (int mf = 0; mf < 4; mf++){
      #pragma unroll
      for (int nf = 0; nf < 8; nf++){
        int bc = nf*8 + qc, jl = mf*16 + qr;
        uint32_t a0 = epi + (uint32_t)(bc*264 + jl*4);
        uint32_t a1 = epi + (uint32_t)((bc+1)*264 + jl*4);
        asm volatile("st.shared.f32 [%0], %1;" :: "r"(a0),      "f"(acc[mf][nf][0]));
        asm volatile("st.shared.f32 [%0], %1;" :: "r"(a1),      "f"(acc[mf][nf][1]));
        asm volatile("st.shared.f32 [%0], %1;" :: "r"(a0 + 32), "f"(acc[mf][nf][2]));
        asm volatile("st.shared.f32 [%0], %1;" :: "r"(a1 + 32), "f"(acc[mf][nf][3]));
      }
    }
    __syncwarp();
    const int c0 = wt*128 + ww*64 + lane*2;
    float2 bb = *reinterpret_cast<const float2*>(aux + c0);
    #pragma unroll 4
    for (int rb = 0; rb < 64; rb++){
      float2 v;
      asm volatile("ld.shared.v2.f32 {%0,%1}, [%2];" : "=f"(v.x), "=f"(v.y)
        : "r"(epi + (uint32_t)(rb*264 + lane*8)));
      v.x += bb.x; v.y += bb.y;
      *reinterpret_cast<float2*>(outF + (size_t)(bt*128 + wb*64 + rb)*4096 + c0) = v;
    }
  }
  #undef LOAD_STAGE
}

// ----------------------------- launch ---------------------------------------
extern "C" void kernel_launch(void* const* d_in, const int* in_sizes, int n_in,
                              void* d_out, int out_size){
  (void)in_sizes; (void)n_in; (void)out_size;
  const float* x    = (const float*)d_in[0];
  const float* V    = (const float*)d_in[1];
  const float* U    = (const float*)d_in[2];
  const float* v2   = (const float*)d_in[3];
  const float* v1   = (const float*)d_in[4];
  const float* u2   = (const float*)d_in[5];
  const float* u1   = (const float*)d_in[6];
  const float* V_R  = (const float*)d_in[7];
  const float* U_R  = (const float*)d_in[8];
  const float* v2_R = (const float*)d_in[9];
  const float* v1_R = (const float*)d_in[10];
  const float* u2_R = (const float*)d_in[11];
  const float* u1_R = (const float*)d_in[12];
  const float* bias = (const float*)d_in[13];
  float* out = (float*)d_out;

  __half *xp, *cv, *cu, *hp; uint32_t *mv, *mu; float* s1;
  cudaGetSymbolAddress((void**)&xp, g_xp);
  cudaGetSymbolAddress((void**)&cv, g_cv);
  cudaGetSymbolAddress((void**)&cu, g_cu);
  cudaGetSymbolAddress((void**)&hp, g_hp);
  cudaGetSymbolAddress((void**)&mv, g_mv);
  cudaGetSymbolAddress((void**)&mu, g_mu);
  cudaGetSymbolAddress((void**)&s1, g_s1);

  prep_all_k<<<PREP_BLOCKS, 256>>>((const float4*)x, (const float4*)v2,
                                   (const float4*)v2_R,
                                   V, V_R, v1, u2, v1_R, u2_R);

  cudaFuncSetAttribute(spgemm_k<0>, cudaFuncAttributeMaxDynamicSharedMemorySize, SMEMB);
  cudaFuncSetAttribute(spgemm_k<1>, cudaFuncAttributeMaxDynamicSharedMemorySize, SMEMB);

  // GEMM1 (+ embedded cu/mu prep in tail CTAs, y in [64,80)):
  dim3 g1(8, 80, 2);   // wtiles x (btiles 64 | prep 16) x branch
  spgemm_k<0><<<g1, 128, SMEMB>>>(cv, mv, xp, 4096,
                                  1024ull*2048, 64ull*128*16, 8192ull*4096,
                                  s1, hp, nullptr,
                                  U, U_R, u1, u1_R);
  // GEMM2: weights = sgn(Ucat)*u1, B = H' -> out + bias
  dim3 g2(32, 64, 1);  // wtiles(4096/128) x btiles
  spgemm_k<1><<<g2, 128, SMEMB>>>(cu, mu, hp, 2048,
                                  0, 0, 0,
                                  bias, nullptr, out,
                                  nullptr, nullptr, nullptr, nullptr);
}